// round 15
// baseline (speedup 1.0000x reference)
#include <cuda_runtime.h>
#include <cuda_bf16.h>
#include <math.h>
#include <stdint.h>

#define H 1024
#define L 4096
#define G3 3072
#define NCTA 64     // CTAs per direction in recurrence
#define UNITS 16    // hidden units per CTA

typedef unsigned long long u64;
typedef unsigned int u32;

// Scratch
__device__ float g_Gi[2][L][G3];              // input projections (~100.7 MB)
__device__ unsigned int g_ctr[2 * L];         // per-step arrival counters (R2 layout)
__device__ float g_h[2][2][H];                // [dir][parity][H] h exchange
__device__ __nv_bfloat16 g_xh[L * H], g_xl[L * H];          // x split
__device__ __nv_bfloat16 g_wh[2][G3 * H], g_wl[2][G3 * H];  // Wih split

// ---------------------------------------------------------------------------
// PTX helpers
// ---------------------------------------------------------------------------
__device__ __forceinline__ void ffma2(u64& acc, u64 a, u64 b) {
    asm("fma.rn.f32x2 %0, %1, %2, %3;" : "=l"(acc) : "l"(a), "l"(b), "l"(acc));
}
__device__ __forceinline__ float hsum2(u64 v) {
    float lo, hi;
    asm("mov.b64 {%0, %1}, %2;" : "=f"(lo), "=f"(hi) : "l"(v));
    return lo + hi;
}
__device__ __forceinline__ void arrive_release(unsigned int* p) {
    asm volatile("red.release.gpu.global.add.u32 [%0], 1;" :: "l"(p) : "memory");
}
__device__ __forceinline__ unsigned int ld_acquire(const unsigned int* p) {
    unsigned int v;
    asm volatile("ld.acquire.gpu.global.u32 %0, [%1];" : "=r"(v) : "l"(p) : "memory");
    return v;
}
__device__ __forceinline__ void st_release_sh(unsigned int* p, unsigned int v) {
    u32 a = (u32)__cvta_generic_to_shared(p);
    asm volatile("st.release.cta.shared::cta.u32 [%0], %1;" :: "r"(a), "r"(v) : "memory");
}
__device__ __forceinline__ unsigned int ld_acquire_sh(const unsigned int* p) {
    u32 a = (u32)__cvta_generic_to_shared(p);
    unsigned int v;
    asm volatile("ld.acquire.cta.shared::cta.u32 %0, [%1];" : "=r"(v) : "r"(a) : "memory");
    return v;
}
// Ampere-era bf16 tensor-core MMA: D(16x8,f32) += A(16x16,bf16) x B(16x8,bf16)
__device__ __forceinline__ void mma_bf16(float& d0, float& d1, float& d2, float& d3,
                                         u32 a0, u32 a1, u32 a2, u32 a3,
                                         u32 b0, u32 b1) {
    asm("mma.sync.aligned.m16n8k16.row.col.f32.bf16.bf16.f32 "
        "{%0,%1,%2,%3}, {%4,%5,%6,%7}, {%8,%9}, {%0,%1,%2,%3};"
        : "+f"(d0), "+f"(d1), "+f"(d2), "+f"(d3)
        : "r"(a0), "r"(a1), "r"(a2), "r"(a3), "r"(b0), "r"(b1));
}
__device__ __forceinline__ void ldsm_x4(u32& r0, u32& r1, u32& r2, u32& r3, u32 addr) {
    asm volatile("ldmatrix.sync.aligned.m8n8.x4.shared.b16 {%0,%1,%2,%3}, [%4];"
        : "=r"(r0), "=r"(r1), "=r"(r2), "=r"(r3) : "r"(addr));
}

// ---------------------------------------------------------------------------
__global__ void dummy_kernel() {}

__global__ void reset_kernel() {
    int i = blockIdx.x * blockDim.x + threadIdx.x;
    for (int k = i; k < 2 * L; k += gridDim.x * blockDim.x) g_ctr[k] = 0u;
}

// ---------------------------------------------------------------------------
// Split fp32 -> bf16 hi/lo for x, Wf, Wr
// ---------------------------------------------------------------------------
__global__ void conv_kernel(const float* __restrict__ x,
                            const float* __restrict__ Wf,
                            const float* __restrict__ Wr) {
    int i = blockIdx.x * blockDim.x + threadIdx.x;
    int stride = gridDim.x * blockDim.x;
    for (int k = i; k < L * H; k += stride) {
        float f = x[k];
        __nv_bfloat16 hi = __float2bfloat16(f);
        g_xh[k] = hi;
        g_xl[k] = __float2bfloat16(f - __bfloat162float(hi));
    }
    for (int k = i; k < G3 * H; k += stride) {
        float f0 = Wf[k];
        __nv_bfloat16 h0 = __float2bfloat16(f0);
        g_wh[0][k] = h0;
        g_wl[0][k] = __float2bfloat16(f0 - __bfloat162float(h0));
        float f1 = Wr[k];
        __nv_bfloat16 h1 = __float2bfloat16(f1);
        g_wh[1][k] = h1;
        g_wl[1][k] = __float2bfloat16(f1 - __bfloat162float(h1));
    }
}

// ---------------------------------------------------------------------------
// Phase 1: Gi = x @ Wih^T + bih via mma.sync bf16-split (3 products, fp32 acc).
// CTA tile 128x128, 8 warps of 32x64, K chunked by 32, ldmatrix loads.
// ---------------------------------------------------------------------------
#define SSTR 40
__global__ __launch_bounds__(256) void gi_gemm_mma(
    const float* __restrict__ bf_, const float* __restrict__ br_)
{
    const int d  = blockIdx.z;
    const int m0 = blockIdx.y * 128;
    const int n0 = blockIdx.x * 128;
    const __nv_bfloat16* __restrict__ xh = g_xh;
    const __nv_bfloat16* __restrict__ xl = g_xl;
    const __nv_bfloat16* __restrict__ wh = g_wh[d];
    const __nv_bfloat16* __restrict__ wl = g_wl[d];

    __shared__ __nv_bfloat16 sAh[128][SSTR], sAl[128][SSTR];
    __shared__ __nv_bfloat16 sBh[128][SSTR], sBl[128][SSTR];

    const int tid  = threadIdx.x;
    const int wid  = tid >> 5, lane = tid & 31;
    const int wm   = wid >> 1, wn = wid & 1;      // warp tile rows wm*32, cols wn*64
    const int r0   = lane >> 2, c0 = (lane & 3) * 2;

    // ldmatrix per-lane base offsets (bytes).
    const int g  = lane >> 3, rr = lane & 7;
    u32 aoff[2];
    #pragma unroll
    for (int mt = 0; mt < 2; ++mt)
        aoff[mt] = (u32)(((wm * 32 + mt * 16 + (g & 1) * 8 + rr) * SSTR
                          + (g >> 1) * 8) * 2);
    u32 boff[4];
    #pragma unroll
    for (int p = 0; p < 4; ++p)
        boff[p] = (u32)(((wn * 64 + p * 16 + (g >> 1) * 8 + rr) * SSTR
                          + (g & 1) * 8) * 2);

    const u32 bAh = (u32)__cvta_generic_to_shared(sAh);
    const u32 bAl = (u32)__cvta_generic_to_shared(sAl);
    const u32 bBh = (u32)__cvta_generic_to_shared(sBh);
    const u32 bBl = (u32)__cvta_generic_to_shared(sBl);

    float acc[2][8][4];
    #pragma unroll
    for (int mt = 0; mt < 2; ++mt)
        #pragma unroll
        for (int nt = 0; nt < 8; ++nt)
            #pragma unroll
            for (int i = 0; i < 4; ++i) acc[mt][nt][i] = 0.0f;

    for (int k0 = 0; k0 < H; k0 += 32) {
        if (k0) __syncthreads();
        #pragma unroll
        for (int it = 0; it < 2; ++it) {
            int idx = tid + it * 256;
            int row = idx >> 2, seg = idx & 3;
            *(uint4*)&sAh[row][seg * 8] =
                *(const uint4*)(xh + (size_t)(m0 + row) * H + k0 + seg * 8);
            *(uint4*)&sAl[row][seg * 8] =
                *(const uint4*)(xl + (size_t)(m0 + row) * H + k0 + seg * 8);
            *(uint4*)&sBh[row][seg * 8] =
                *(const uint4*)(wh + (size_t)(n0 + row) * H + k0 + seg * 8);
            *(uint4*)&sBl[row][seg * 8] =
                *(const uint4*)(wl + (size_t)(n0 + row) * H + k0 + seg * 8);
        }
        __syncthreads();

        #pragma unroll
        for (int kk = 0; kk < 32; kk += 16) {
            const u32 kb = (u32)(kk * 2);
            u32 ah[2][4], al[2][4], bh[8][2], bl[8][2];
            #pragma unroll
            for (int mt = 0; mt < 2; ++mt) {
                ldsm_x4(ah[mt][0], ah[mt][1], ah[mt][2], ah[mt][3], bAh + aoff[mt] + kb);
                ldsm_x4(al[mt][0], al[mt][1], al[mt][2], al[mt][3], bAl + aoff[mt] + kb);
            }
            #pragma unroll
            for (int p = 0; p < 4; ++p) {
                ldsm_x4(bh[2*p][0], bh[2*p][1], bh[2*p+1][0], bh[2*p+1][1], bBh + boff[p] + kb);
                ldsm_x4(bl[2*p][0], bl[2*p][1], bl[2*p+1][0], bl[2*p+1][1], bBl + boff[p] + kb);
            }
            #pragma unroll
            for (int mt = 0; mt < 2; ++mt)
                #pragma unroll
                for (int nt = 0; nt < 8; ++nt) {
                    float* a = acc[mt][nt];
                    mma_bf16(a[0], a[1], a[2], a[3],
                             ah[mt][0], ah[mt][1], ah[mt][2], ah[mt][3],
                             bh[nt][0], bh[nt][1]);
                    mma_bf16(a[0], a[1], a[2], a[3],
                             ah[mt][0], ah[mt][1], ah[mt][2], ah[mt][3],
                             bl[nt][0], bl[nt][1]);
                    mma_bf16(a[0], a[1], a[2], a[3],
                             al[mt][0], al[mt][1], al[mt][2], al[mt][3],
                             bh[nt][0], bh[nt][1]);
                }
        }
    }

    float* __restrict__ C = &g_Gi[d][0][0];
    const float* __restrict__ bias = d ? br_ : bf_;
    #pragma unroll
    for (int mt = 0; mt < 2; ++mt) {
        #pragma unroll
        for (int nt = 0; nt < 8; ++nt) {
            int row = m0 + wm * 32 + mt * 16 + r0;
            int col = n0 + wn * 64 + nt * 8 + c0;
            float b0v = __ldg(bias + col);
            float b1v = __ldg(bias + col + 1);
            float2 o0, o1;
            o0.x = acc[mt][nt][0] + b0v; o0.y = acc[mt][nt][1] + b1v;
            o1.x = acc[mt][nt][2] + b0v; o1.y = acc[mt][nt][3] + b1v;
            *(float2*)(C + (size_t)row * G3 + col)       = o0;
            *(float2*)(C + (size_t)(row + 8) * G3 + col) = o1;
        }
    }
}

// ---------------------------------------------------------------------------
// Phase 2: persistent register-resident GRU recurrence (golden R2 skeleton).
// Change: poll result broadcast via SMEM release/acquire flag instead of a
// __syncthreads -> one fewer barrier on the critical chain.
// ---------------------------------------------------------------------------
__device__ __forceinline__ float sigm(float v) {
    return 1.0f / (1.0f + __expf(-v));
}
__device__ __forceinline__ float tanh_fast(float v) {
    return 2.0f / (1.0f + __expf(-2.0f * v)) - 1.0f;
}

__global__ __launch_bounds__(512, 1) void gru_recur(
    const float* __restrict__ Whh_f, const float* __restrict__ bhh_f,
    const float* __restrict__ Whh_r, const float* __restrict__ bhh_r,
    float* __restrict__ out)
{
    const int bx  = blockIdx.x;
    const int d   = (bx >= NCTA) ? 1 : 0;
    const int cta = d ? bx - NCTA : bx;
    const int u0  = cta * UNITS;
    const int tid = threadIdx.x;
    const int w   = tid >> 5;
    const int l   = tid & 31;
    const int u   = u0 + w;

    const float* __restrict__ Whh = d ? Whh_r : Whh_f;
    const float* __restrict__ bhh = d ? bhh_r : bhh_f;
    const float* __restrict__ Gi  = &g_Gi[d][0][0];
    unsigned int* ctr = g_ctr + d * L;
    float* hbuf0 = &g_h[d][0][0];
    float* hbuf1 = &g_h[d][1][0];

    __shared__ float h_s[H];
    __shared__ unsigned int s_go;      // step-ready flag (rel/acq within CTA)
    const u64* hs64 = (const u64*)h_s;

    if (tid == 0) s_go = 0u;

    u64 w0[16], w1[16], w2[16];
    {
        const u64* r0 = (const u64*)(Whh + (size_t)(u         ) * H + 4 * l);
        const u64* r1 = (const u64*)(Whh + (size_t)(u + H     ) * H + 4 * l);
        const u64* r2 = (const u64*)(Whh + (size_t)(u + 2 * H ) * H + 4 * l);
        #pragma unroll
        for (int c = 0; c < 8; ++c) {
            w0[2*c] = r0[c*64]; w0[2*c+1] = r0[c*64+1];
            w1[2*c] = r1[c*64]; w1[2*c+1] = r1[c*64+1];
            w2[2*c] = r2[c*64]; w2[2*c+1] = r2[c*64+1];
        }
    }
    const float b_r = bhh[u];
    const float b_z = bhh[u + H];
    const float b_n = bhh[u + 2 * H];

    __syncthreads();   // s_go init visible

    for (int s = 0; s < L; ++s) {
        const int t = d ? (L - 1 - s) : s;

        float gi_r = 0.f, gi_z = 0.f, gi_n = 0.f;
        if (l == 0) {
            const float* g = Gi + (size_t)t * G3;
            gi_r = __ldg(g + u);
            gi_z = __ldg(g + u + H);
            gi_n = __ldg(g + u + 2 * H);
        }

        if (s == 0) {
            if (tid < 256) ((float4*)h_s)[tid] = make_float4(0.f, 0.f, 0.f, 0.f);
        } else {
            if (tid == 0) {
                while (ld_acquire(&ctr[s - 1]) < (unsigned)NCTA) { }
                st_release_sh(&s_go, (unsigned)s);     // broadcast, no barrier
            } else {
                while (ld_acquire_sh(&s_go) < (unsigned)s) { }
            }
            const float4* src = (const float4*)(((s - 1) & 1) ? hbuf1 : hbuf0);
            if (tid < 256) ((float4*)h_s)[tid] = __ldcg(src + tid);
        }
        __syncthreads();

        u64 a0 = 0ull, a1 = 0ull, a2 = 0ull;
        #pragma unroll
        for (int c = 0; c < 8; ++c) {
            u64 h0 = hs64[c * 64 + 2 * l];
            u64 h1 = hs64[c * 64 + 2 * l + 1];
            ffma2(a0, w0[2*c], h0); ffma2(a0, w0[2*c+1], h1);
            ffma2(a1, w1[2*c], h0); ffma2(a1, w1[2*c+1], h1);
            ffma2(a2, w2[2*c], h0); ffma2(a2, w2[2*c+1], h1);
        }
        float s0 = hsum2(a0), s1 = hsum2(a1), s2 = hsum2(a2);
        #pragma unroll
        for (int o = 16; o > 0; o >>= 1) {
            s0 += __shfl_xor_sync(0xffffffffu, s0, o);
            s1 += __shfl_xor_sync(0xffffffffu, s1, o);
            s2 += __shfl_xor_sync(0xffffffffu, s2, o);
        }

        float hn = 0.f;
        if (l == 0) {
            float r  = sigm(gi_r + s0 + b_r);
            float z  = sigm(gi_z + s1 + b_z);
            float n  = tanh_fast(gi_n + r * (s2 + b_n));
            float hp = h_s[u];
            hn = fmaf(z, hp - n, n);   // (1-z)*n + z*hp
            __stcg(((s & 1) ? hbuf1 : hbuf0) + u, hn);
        }

        __syncthreads();
        if (tid == 0) arrive_release(&ctr[s]);

        // Off the critical path: outputs after signaling.
        if (l == 0) {
            out[(size_t)t * (2 * H) + d * H + u] = hn;
            if (s == L - 1) {
                const size_t hid_off = (size_t)L * (2 * H);
                out[hid_off + d * H + u]         = hn;
                out[hid_off + 2 * H + d * H + u] = hn;
            }
        }
    }
}

// ---------------------------------------------------------------------------
// Launch
// ---------------------------------------------------------------------------
extern "C" void kernel_launch(void* const* d_in, const int* in_sizes, int n_in,
                              void* d_out, int out_size)
{
    const float* x    = (const float*)d_in[0];
    const float* fWih = (const float*)d_in[1];
    const float* fWhh = (const float*)d_in[2];
    const float* fbih = (const float*)d_in[3];
    const float* fbhh = (const float*)d_in[4];
    const float* rWih = (const float*)d_in[5];
    const float* rWhh = (const float*)d_in[6];
    const float* rbih = (const float*)d_in[7];
    const float* rbhh = (const float*)d_in[8];
    float* out = (float*)d_out;

    dummy_kernel<<<1, 32>>>();
    reset_kernel<<<8, 256>>>();
    conv_kernel<<<1024, 256>>>(x, fWih, rWih);

    dim3 ggrid(G3 / 128, L / 128, 2);
    gi_gemm_mma<<<ggrid, 256>>>(fbih, rbih);

    gru_recur<<<2 * NCTA, 512>>>(fWhh, fbhh, rWhh, rbhh, out);
}

// round 16
// speedup vs baseline: 1.0817x; 1.0817x over previous
#include <cuda_runtime.h>
#include <cuda_bf16.h>
#include <math.h>
#include <stdint.h>

#define H 1024
#define L 4096
#define G3 3072
#define NCTA 64     // CTAs per direction in recurrence
#define UNITS 16    // hidden units per CTA

typedef unsigned long long u64;
typedef unsigned int u32;

// Scratch
__device__ float g_Gi[2][L][G3];              // input projections (~100.7 MB)
__device__ unsigned int g_ctr[2 * L];         // per-step arrival counters (R2 layout)
__device__ float g_h[2][2][H];                // [dir][parity][H] h exchange
__device__ __nv_bfloat16 g_xh[L * H], g_xl[L * H];          // x split
__device__ __nv_bfloat16 g_wh[2][G3 * H], g_wl[2][G3 * H];  // Wih split

// ---------------------------------------------------------------------------
// PTX helpers
// ---------------------------------------------------------------------------
__device__ __forceinline__ void ffma2(u64& acc, u64 a, u64 b) {
    asm("fma.rn.f32x2 %0, %1, %2, %3;" : "=l"(acc) : "l"(a), "l"(b), "l"(acc));
}
__device__ __forceinline__ float hsum2(u64 v) {
    float lo, hi;
    asm("mov.b64 {%0, %1}, %2;" : "=f"(lo), "=f"(hi) : "l"(v));
    return lo + hi;
}
__device__ __forceinline__ void arrive_release(unsigned int* p) {
    asm volatile("red.release.gpu.global.add.u32 [%0], 1;" :: "l"(p) : "memory");
}
__device__ __forceinline__ unsigned int ld_acquire(const unsigned int* p) {
    unsigned int v;
    asm volatile("ld.acquire.gpu.global.u32 %0, [%1];" : "=r"(v) : "l"(p) : "memory");
    return v;
}
__device__ __forceinline__ void mma_bf16(float& d0, float& d1, float& d2, float& d3,
                                         u32 a0, u32 a1, u32 a2, u32 a3,
                                         u32 b0, u32 b1) {
    asm("mma.sync.aligned.m16n8k16.row.col.f32.bf16.bf16.f32 "
        "{%0,%1,%2,%3}, {%4,%5,%6,%7}, {%8,%9}, {%0,%1,%2,%3};"
        : "+f"(d0), "+f"(d1), "+f"(d2), "+f"(d3)
        : "r"(a0), "r"(a1), "r"(a2), "r"(a3), "r"(b0), "r"(b1));
}
__device__ __forceinline__ void ldsm_x4(u32& r0, u32& r1, u32& r2, u32& r3, u32 addr) {
    asm volatile("ldmatrix.sync.aligned.m8n8.x4.shared.b16 {%0,%1,%2,%3}, [%4];"
        : "=r"(r0), "=r"(r1), "=r"(r2), "=r"(r3) : "r"(addr));
}
__device__ __forceinline__ void cp16(u32 dst, const void* src) {
    asm volatile("cp.async.cg.shared.global [%0], [%1], 16;" :: "r"(dst), "l"(src));
}

// ---------------------------------------------------------------------------
__global__ void dummy_kernel() {}

__global__ void reset_kernel() {
    int i = blockIdx.x * blockDim.x + threadIdx.x;
    for (int k = i; k < 2 * L; k += gridDim.x * blockDim.x) g_ctr[k] = 0u;
}

// ---------------------------------------------------------------------------
// Split fp32 -> bf16 hi/lo for x, Wf, Wr
// ---------------------------------------------------------------------------
__global__ void conv_kernel(const float* __restrict__ x,
                            const float* __restrict__ Wf,
                            const float* __restrict__ Wr) {
    int i = blockIdx.x * blockDim.x + threadIdx.x;
    int stride = gridDim.x * blockDim.x;
    for (int k = i; k < L * H; k += stride) {
        float f = x[k];
        __nv_bfloat16 hi = __float2bfloat16(f);
        g_xh[k] = hi;
        g_xl[k] = __float2bfloat16(f - __bfloat162float(hi));
    }
    for (int k = i; k < G3 * H; k += stride) {
        float f0 = Wf[k];
        __nv_bfloat16 h0 = __float2bfloat16(f0);
        g_wh[0][k] = h0;
        g_wl[0][k] = __float2bfloat16(f0 - __bfloat162float(h0));
        float f1 = Wr[k];
        __nv_bfloat16 h1 = __float2bfloat16(f1);
        g_wh[1][k] = h1;
        g_wl[1][k] = __float2bfloat16(f1 - __bfloat162float(h1));
    }
}

// ---------------------------------------------------------------------------
// Phase 1: Gi = x @ Wih^T + bih via mma.sync bf16-split (3 products, fp32 acc).
// CTA tile 128x64 (R13 geometry), cp.async double-buffered K chunks of 32.
// ---------------------------------------------------------------------------
#define SSTR 40
__global__ __launch_bounds__(256) void gi_gemm_mma(
    const float* __restrict__ bf_, const float* __restrict__ br_)
{
    const int d  = blockIdx.z;
    const int m0 = blockIdx.y * 128;
    const int n0 = blockIdx.x * 64;
    const __nv_bfloat16* __restrict__ xh = g_xh;
    const __nv_bfloat16* __restrict__ xl = g_xl;
    const __nv_bfloat16* __restrict__ wh = g_wh[d];
    const __nv_bfloat16* __restrict__ wl = g_wl[d];

    // [stage][hi/lo][row][col]
    __shared__ __nv_bfloat16 sA[2][2][128][SSTR];
    __shared__ __nv_bfloat16 sB[2][2][64][SSTR];

    const int tid  = threadIdx.x;
    const int wid  = tid >> 5, lane = tid & 31;
    const int wm   = wid >> 1, wn = wid & 1;
    const int r0   = lane >> 2, c0 = (lane & 3) * 2;

    // ldmatrix per-lane offsets (bytes) within one [128][SSTR] / [64][SSTR] tile.
    const int g  = lane >> 3, rr = lane & 7;
    u32 aoff[2];
    #pragma unroll
    for (int mt = 0; mt < 2; ++mt)
        aoff[mt] = (u32)(((wm * 32 + mt * 16 + (g & 1) * 8 + rr) * SSTR
                          + (g >> 1) * 8) * 2);
    u32 boff[2];
    #pragma unroll
    for (int p = 0; p < 2; ++p)
        boff[p] = (u32)(((wn * 32 + p * 16 + (g >> 1) * 8 + rr) * SSTR
                          + (g & 1) * 8) * 2);

    const u32 bA0 = (u32)__cvta_generic_to_shared(&sA[0][0][0][0]);
    const u32 bB0 = (u32)__cvta_generic_to_shared(&sB[0][0][0][0]);
    const u32 A_STAGE = 2u * 128u * SSTR * 2u;   // bytes per A stage (hi+lo)
    const u32 A_MAT   = 128u * SSTR * 2u;
    const u32 B_STAGE = 2u * 64u * SSTR * 2u;
    const u32 B_MAT   = 64u * SSTR * 2u;

    // Per-thread cp.async assignments.
    const int arow0 = tid >> 1, aseg0 = (tid & 1) * 2;         // A: 2 chunks of 16B
    const int brow  = tid >> 2, bseg = tid & 3;                // B: 1 chunk of 16B

    float acc[2][4][4];
    #pragma unroll
    for (int mt = 0; mt < 2; ++mt)
        #pragma unroll
        for (int nt = 0; nt < 4; ++nt)
            #pragma unroll
            for (int i = 0; i < 4; ++i) acc[mt][nt][i] = 0.0f;

    auto load_stage = [&](int ch, int st) {
        const int k0 = ch * 32;
        // A hi/lo: rows arow0, 2x16B each
        #pragma unroll
        for (int q = 0; q < 2; ++q) {
            u32 doff = (u32)(arow0 * (SSTR * 2) + (aseg0 + q) * 16);
            cp16(bA0 + st * A_STAGE + doff,
                 xh + (size_t)(m0 + arow0) * H + k0 + (aseg0 + q) * 8);
            cp16(bA0 + st * A_STAGE + A_MAT + doff,
                 xl + (size_t)(m0 + arow0) * H + k0 + (aseg0 + q) * 8);
        }
        // B hi/lo: 1x16B each
        {
            u32 doff = (u32)(brow * (SSTR * 2) + bseg * 16);
            cp16(bB0 + st * B_STAGE + doff,
                 wh + (size_t)(n0 + brow) * H + k0 + bseg * 8);
            cp16(bB0 + st * B_STAGE + B_MAT + doff,
                 wl + (size_t)(n0 + brow) * H + k0 + bseg * 8);
        }
        asm volatile("cp.async.commit_group;");
    };

    load_stage(0, 0);

    for (int ch = 0; ch < H / 32; ++ch) {
        const int st = ch & 1;
        if (ch + 1 < H / 32) {
            load_stage(ch + 1, st ^ 1);
            asm volatile("cp.async.wait_group 1;");
        } else {
            asm volatile("cp.async.wait_group 0;");
        }
        __syncthreads();

        const u32 Ah = bA0 + st * A_STAGE;
        const u32 Al = Ah + A_MAT;
        const u32 Bh = bB0 + st * B_STAGE;
        const u32 Bl = Bh + B_MAT;

        #pragma unroll
        for (int kk = 0; kk < 32; kk += 16) {
            const u32 kb = (u32)(kk * 2);
            u32 ah[2][4], al[2][4], bh[4][2], bl[4][2];
            #pragma unroll
            for (int mt = 0; mt < 2; ++mt) {
                ldsm_x4(ah[mt][0], ah[mt][1], ah[mt][2], ah[mt][3], Ah + aoff[mt] + kb);
                ldsm_x4(al[mt][0], al[mt][1], al[mt][2], al[mt][3], Al + aoff[mt] + kb);
            }
            #pragma unroll
            for (int p = 0; p < 2; ++p) {
                ldsm_x4(bh[2*p][0], bh[2*p][1], bh[2*p+1][0], bh[2*p+1][1], Bh + boff[p] + kb);
                ldsm_x4(bl[2*p][0], bl[2*p][1], bl[2*p+1][0], bl[2*p+1][1], Bl + boff[p] + kb);
            }
            #pragma unroll
            for (int mt = 0; mt < 2; ++mt)
                #pragma unroll
                for (int nt = 0; nt < 4; ++nt) {
                    float* a = acc[mt][nt];
                    mma_bf16(a[0], a[1], a[2], a[3],
                             ah[mt][0], ah[mt][1], ah[mt][2], ah[mt][3],
                             bh[nt][0], bh[nt][1]);
                    mma_bf16(a[0], a[1], a[2], a[3],
                             ah[mt][0], ah[mt][1], ah[mt][2], ah[mt][3],
                             bl[nt][0], bl[nt][1]);
                    mma_bf16(a[0], a[1], a[2], a[3],
                             al[mt][0], al[mt][1], al[mt][2], al[mt][3],
                             bh[nt][0], bh[nt][1]);
                }
        }
        __syncthreads();   // all reads of stage st done before it is refilled
    }

    float* __restrict__ C = &g_Gi[d][0][0];
    const float* __restrict__ bias = d ? br_ : bf_;
    #pragma unroll
    for (int mt = 0; mt < 2; ++mt) {
        #pragma unroll
        for (int nt = 0; nt < 4; ++nt) {
            int row = m0 + wm * 32 + mt * 16 + r0;
            int col = n0 + wn * 32 + nt * 8 + c0;
            float b0v = __ldg(bias + col);
            float b1v = __ldg(bias + col + 1);
            float2 o0, o1;
            o0.x = acc[mt][nt][0] + b0v; o0.y = acc[mt][nt][1] + b1v;
            o1.x = acc[mt][nt][2] + b0v; o1.y = acc[mt][nt][3] + b1v;
            *(float2*)(C + (size_t)row * G3 + col)       = o0;
            *(float2*)(C + (size_t)(row + 8) * G3 + col) = o1;
        }
    }
}

// ---------------------------------------------------------------------------
// Phase 2: persistent register-resident GRU recurrence — golden R2/R13.
// ---------------------------------------------------------------------------
__device__ __forceinline__ float sigm(float v) {
    return 1.0f / (1.0f + __expf(-v));
}
__device__ __forceinline__ float tanh_fast(float v) {
    return 2.0f / (1.0f + __expf(-2.0f * v)) - 1.0f;
}

__global__ __launch_bounds__(512, 1) void gru_recur(
    const float* __restrict__ Whh_f, const float* __restrict__ bhh_f,
    const float* __restrict__ Whh_r, const float* __restrict__ bhh_r,
    float* __restrict__ out)
{
    const int bx  = blockIdx.x;
    const int d   = (bx >= NCTA) ? 1 : 0;
    const int cta = d ? bx - NCTA : bx;
    const int u0  = cta * UNITS;
    const int tid = threadIdx.x;
    const int w   = tid >> 5;
    const int l   = tid & 31;
    const int u   = u0 + w;

    const float* __restrict__ Whh = d ? Whh_r : Whh_f;
    const float* __restrict__ bhh = d ? bhh_r : bhh_f;
    const float* __restrict__ Gi  = &g_Gi[d][0][0];
    unsigned int* ctr = g_ctr + d * L;
    float* hbuf0 = &g_h[d][0][0];
    float* hbuf1 = &g_h[d][1][0];

    __shared__ float h_s[H];
    const u64* hs64 = (const u64*)h_s;

    u64 w0[16], w1[16], w2[16];
    {
        const u64* r0 = (const u64*)(Whh + (size_t)(u         ) * H + 4 * l);
        const u64* r1 = (const u64*)(Whh + (size_t)(u + H     ) * H + 4 * l);
        const u64* r2 = (const u64*)(Whh + (size_t)(u + 2 * H ) * H + 4 * l);
        #pragma unroll
        for (int c = 0; c < 8; ++c) {
            w0[2*c] = r0[c*64]; w0[2*c+1] = r0[c*64+1];
            w1[2*c] = r1[c*64]; w1[2*c+1] = r1[c*64+1];
            w2[2*c] = r2[c*64]; w2[2*c+1] = r2[c*64+1];
        }
    }
    const float b_r = bhh[u];
    const float b_z = bhh[u + H];
    const float b_n = bhh[u + 2 * H];

    for (int s = 0; s < L; ++s) {
        const int t = d ? (L - 1 - s) : s;

        float gi_r = 0.f, gi_z = 0.f, gi_n = 0.f;
        if (l == 0) {
            const float* g = Gi + (size_t)t * G3;
            gi_r = __ldg(g + u);
            gi_z = __ldg(g + u + H);
            gi_n = __ldg(g + u + 2 * H);
        }

        if (s == 0) {
            if (tid < 256) ((float4*)h_s)[tid] = make_float4(0.f, 0.f, 0.f, 0.f);
        } else {
            if (tid == 0) {
                while (ld_acquire(&ctr[s - 1]) < (unsigned)NCTA) { }
            }
            __syncthreads();
            const float4* src = (const float4*)(((s - 1) & 1) ? hbuf1 : hbuf0);
            if (tid < 256) ((float4*)h_s)[tid] = __ldcg(src + tid);
        }
        __syncthreads();

        u64 a0 = 0ull, a1 = 0ull, a2 = 0ull;
        #pragma unroll
        for (int c = 0; c < 8; ++c) {
            u64 h0 = hs64[c * 64 + 2 * l];
            u64 h1 = hs64[c * 64 + 2 * l + 1];
            ffma2(a0, w0[2*c], h0); ffma2(a0, w0[2*c+1], h1);
            ffma2(a1, w1[2*c], h0); ffma2(a1, w1[2*c+1], h1);
            ffma2(a2, w2[2*c], h0); ffma2(a2, w2[2*c+1], h1);
        }
        float s0 = hsum2(a0), s1 = hsum2(a1), s2 = hsum2(a2);
        #pragma unroll
        for (int o = 16; o > 0; o >>= 1) {
            s0 += __shfl_xor_sync(0xffffffffu, s0, o);
            s1 += __shfl_xor_sync(0xffffffffu, s1, o);
            s2 += __shfl_xor_sync(0xffffffffu, s2, o);
        }

        if (l == 0) {
            float r  = sigm(gi_r + s0 + b_r);
            float z  = sigm(gi_z + s1 + b_z);
            float n  = tanh_fast(gi_n + r * (s2 + b_n));
            float hp = h_s[u];
            float hn = fmaf(z, hp - n, n);   // (1-z)*n + z*hp
            __stcg(((s & 1) ? hbuf1 : hbuf0) + u, hn);
            out[(size_t)t * (2 * H) + d * H + u] = hn;
            if (s == L - 1) {
                const size_t hid_off = (size_t)L * (2 * H);
                out[hid_off + d * H + u]         = hn;
                out[hid_off + 2 * H + d * H + u] = hn;
            }
        }

        __syncthreads();
        if (tid == 0) arrive_release(&ctr[s]);
    }
}

// ---------------------------------------------------------------------------
// Launch
// ---------------------------------------------------------------------------
extern "C" void kernel_launch(void* const* d_in, const int* in_sizes, int n_in,
                              void* d_out, int out_size)
{
    const float* x    = (const float*)d_in[0];
    const float* fWih = (const float*)d_in[1];
    const float* fWhh = (const float*)d_in[2];
    const float* fbih = (const float*)d_in[3];
    const float* fbhh = (const float*)d_in[4];
    const float* rWih = (const float*)d_in[5];
    const float* rWhh = (const float*)d_in[6];
    const float* rbih = (const float*)d_in[7];
    const float* rbhh = (const float*)d_in[8];
    float* out = (float*)d_out;

    dummy_kernel<<<1, 32>>>();
    reset_kernel<<<8, 256>>>();
    conv_kernel<<<1024, 256>>>(x, fWih, rWih);

    dim3 ggrid(G3 / 64, L / 128, 2);
    gi_gemm_mma<<<ggrid, 256>>>(fbih, rbih);

    gru_recur<<<2 * NCTA, 512>>>(fWhh, fbhh, rWhh, rbhh, out);
}